// round 1
// baseline (speedup 1.0000x reference)
#include <cuda_runtime.h>
#include <math.h>

#define H     300
#define G     900          // 3*H
#define NB    1024         // graphs
#define LSEQ  64           // max sequence length
#define BTR   16           // graphs per recurrent CTA
#define BTG   32           // padded rows per input-GEMM CTA
#define NTHREADS 320       // 10 warps, 300 active compute lanes

typedef unsigned long long ull;

// ---------------- packed f32x2 helpers (Blackwell FFMA2 via PTX) ----------------
__device__ __forceinline__ ull fma2(ull a, ull b, ull c) {
    ull d; asm("fma.rn.f32x2 %0, %1, %2, %3;" : "=l"(d) : "l"(a), "l"(b), "l"(c)); return d;
}
__device__ __forceinline__ ull pack2(float x, float y) {
    ull d; asm("mov.b64 %0, {%1, %2};" : "=l"(d) : "f"(x), "f"(y)); return d;
}
__device__ __forceinline__ float2 unpack2(ull a) {
    float2 r; asm("mov.b64 {%0, %1}, %2;" : "=f"(r.x), "=f"(r.y) : "l"(a)); return r;
}
__device__ __forceinline__ float sigm(float x) { return 1.f / (1.f + __expf(-x)); }

// ---------------- device scratch (static: no allocations allowed) ----------------
// padded messages, tile-transposed: [tile = m>>5][k][32] with m = b*64 + t
__device__ float g_x[(size_t)NB * LSEQ * H];
// input-gate preactivations, time-major: [dir][t][b][g]
__device__ float g_xg[2][(size_t)NB * LSEQ * G];
__device__ float g_wt_ih[2][H * G];   // k-major transposed w_ih
__device__ float g_wt_hh[2][H * G];   // k-major transposed w_hh
__device__ float g_h0[NB * H];
__device__ int   g_sstart[NB];
__device__ int   g_slen[NB];

// ---------------- 1) zero padded buffer ----------------
__global__ void k_zero_x() {
    size_t n4 = (size_t)NB * LSEQ * H / 4;
    float4* p = (float4*)g_x;
    float4 z = make_float4(0.f, 0.f, 0.f, 0.f);
    for (size_t i = (size_t)blockIdx.x * blockDim.x + threadIdx.x; i < n4;
         i += (size_t)gridDim.x * blockDim.x) p[i] = z;
}

// ---------------- 2) segment bounds (batch is sorted, no atomics) ----------------
__global__ void k_seg(const int* __restrict__ batch, const int* __restrict__ pos, int n) {
    int i = blockIdx.x * blockDim.x + threadIdx.x;
    if (i >= n) return;
    int b = batch[i];
    if (pos[i] == 0) g_sstart[b] = i;
    if (i == n - 1 || batch[i + 1] != b) g_slen[b] = pos[i] + 1;
}

// ---------------- 3) message = relu(node + bias), scattered + tile-transposed ----------------
__global__ void k_message(const float* __restrict__ node, const int* __restrict__ batch,
                          const int* __restrict__ pos, const float* __restrict__ bias, int n) {
    int tot = n * H;
    for (int idx = blockIdx.x * blockDim.x + threadIdx.x; idx < tot;
         idx += gridDim.x * blockDim.x) {
        int i = idx / H, h = idx - i * H;
        int m = batch[i] * LSEQ + pos[i];
        float v = node[idx] + bias[h];
        g_x[((size_t)(m >> 5) * H + h) * BTG + (m & 31)] = v > 0.f ? v : 0.f;
    }
}

// ---------------- 4) h0 = per-graph segment max ----------------
__global__ void __launch_bounds__(NTHREADS) k_h0(const float* __restrict__ node) {
    int b = blockIdx.x, h = threadIdx.x;
    if (h >= H) return;
    int s = g_sstart[b], l = g_slen[b];
    float m = -3.402823466e38f;
    for (int i = 0; i < l; ++i) m = fmaxf(m, node[(size_t)(s + i) * H + h]);
    g_h0[b * H + h] = m;
}

// ---------------- 5) weight transpose to k-major [k][g] ----------------
__global__ void k_transpose(const float* __restrict__ wif, const float* __restrict__ whf,
                            const float* __restrict__ wib, const float* __restrict__ whb) {
    const int tot = 4 * H * G;
    for (int idx = blockIdx.x * blockDim.x + threadIdx.x; idx < tot;
         idx += gridDim.x * blockDim.x) {
        int sel = idx / (H * G), r = idx - sel * (H * G);
        int g = r / H, k = r - g * H;
        const float* src = (sel == 0) ? wif : (sel == 1) ? whf : (sel == 2) ? wib : whb;
        float* dst = (sel == 0) ? g_wt_ih[0] : (sel == 1) ? g_wt_hh[0]
                   : (sel == 2) ? g_wt_ih[1] : g_wt_hh[1];
        dst[k * G + g] = src[r];
    }
}

// ---------------- 6) input-side GEMM: xg[d][t][b][g] = x @ w_ih^T + b_ih ----------------
__global__ void __launch_bounds__(NTHREADS) k_gemm16(const float* __restrict__ bih_f,
                                                     const float* __restrict__ bih_b) {
    int dir = blockIdx.y;
    int tile = blockIdx.x;              // 2048 tiles of 32 padded rows
    __shared__ float sx[H * BTG];       // [k][32]
    {
        const float4* src = (const float4*)(g_x + (size_t)tile * H * BTG);
        float4* dst = (float4*)sx;
        for (int u = threadIdx.x; u < H * BTG / 4; u += NTHREADS) dst[u] = src[u];
    }
    __syncthreads();
    int j = threadIdx.x;
    if (j >= H) return;

    const float* __restrict__ w0 = g_wt_ih[dir] + j;
    ull a0[16], a1[16], a2[16];
#pragma unroll
    for (int p = 0; p < 16; ++p) { a0[p] = 0ull; a1[p] = 0ull; a2[p] = 0ull; }

#pragma unroll 2
    for (int k = 0; k < H; ++k) {
        float wr = w0[k * G], wz = w0[k * G + H], wn = w0[k * G + 2 * H];
        ull wrp = pack2(wr, wr), wzp = pack2(wz, wz), wnp = pack2(wn, wn);
        const ulonglong2* hp = (const ulonglong2*)(sx + k * BTG);
#pragma unroll
        for (int q = 0; q < 8; ++q) {
            ulonglong2 hv = hp[q];
            a0[2*q]   = fma2(wrp, hv.x, a0[2*q]);
            a0[2*q+1] = fma2(wrp, hv.y, a0[2*q+1]);
            a1[2*q]   = fma2(wzp, hv.x, a1[2*q]);
            a1[2*q+1] = fma2(wzp, hv.y, a1[2*q+1]);
            a2[2*q]   = fma2(wnp, hv.x, a2[2*q]);
            a2[2*q+1] = fma2(wnp, hv.y, a2[2*q+1]);
        }
    }

    const float* bih = dir ? bih_b : bih_f;
    float bi0 = bih[j], bi1 = bih[H + j], bi2 = bih[2 * H + j];
    float* xg = g_xg[dir];
    int m0 = tile * BTG;
    int b  = m0 >> 6;                   // graph id (constant within tile: 32 | 64)
    int t0 = m0 & 63;
#pragma unroll
    for (int p = 0; p < 16; ++p) {
        float2 v0 = unpack2(a0[p]), v1 = unpack2(a1[p]), v2 = unpack2(a2[p]);
        int t = t0 + 2 * p;
        float* r0 = xg + ((size_t)t * NB + b) * G;
        float* r1 = xg + ((size_t)(t + 1) * NB + b) * G;
        r0[j] = v0.x + bi0; r0[H + j] = v1.x + bi1; r0[2 * H + j] = v2.x + bi2;
        r1[j] = v0.y + bi0; r1[H + j] = v1.y + bi1; r1[2 * H + j] = v2.y + bi2;
    }
}

// ---------------- 7) recurrent GRU, both directions, batch-partitioned ----------------
__global__ void __launch_bounds__(NTHREADS, 1) k_recur(const float* __restrict__ bhh_f,
                                                       const float* __restrict__ bhh_b,
                                                       float* __restrict__ out) {
    int dir = blockIdx.y;
    int b0 = blockIdx.x * BTR;
    __shared__ float sh[H * BTR];       // h, k-major: sh[k*16 + b]
    __shared__ int sstart[BTR], slen[BTR];

    for (int u = threadIdx.x; u < H * BTR; u += NTHREADS) {
        int k = u / BTR, b = u - k * BTR;
        sh[u] = g_h0[(b0 + b) * H + k];
    }
    if (threadIdx.x < BTR) {
        sstart[threadIdx.x] = g_sstart[b0 + threadIdx.x];
        slen[threadIdx.x]   = g_slen[b0 + threadIdx.x];
    }
    __syncthreads();

    int j = threadIdx.x;                // hidden unit owned by this thread
    const float* __restrict__ w0 = g_wt_hh[dir] + j;
    const float* __restrict__ bhh = dir ? bhh_b : bhh_f;
    const float* __restrict__ xg = g_xg[dir];
    float bh0 = 0.f, bh1 = 0.f, bh2 = 0.f;
    if (j < H) { bh0 = bhh[j]; bh1 = bhh[H + j]; bh2 = bhh[2 * H + j]; }

    for (int s = 0; s < LSEQ; ++s) {
        int t = dir ? (LSEQ - 1 - s) : s;
        float hn[BTR];
        if (j < H) {
            ull a0[8], a1[8], a2[8];
#pragma unroll
            for (int p = 0; p < 8; ++p) { a0[p] = 0ull; a1[p] = 0ull; a2[p] = 0ull; }
#pragma unroll 2
            for (int k = 0; k < H; ++k) {
                float wr = w0[k * G], wz = w0[k * G + H], wn = w0[k * G + 2 * H];
                ull wrp = pack2(wr, wr), wzp = pack2(wz, wz), wnp = pack2(wn, wn);
                const ulonglong2* hp = (const ulonglong2*)(sh + k * BTR);
#pragma unroll
                for (int q = 0; q < 4; ++q) {
                    ulonglong2 hv = hp[q];
                    a0[2*q]   = fma2(wrp, hv.x, a0[2*q]);
                    a0[2*q+1] = fma2(wrp, hv.y, a0[2*q+1]);
                    a1[2*q]   = fma2(wzp, hv.x, a1[2*q]);
                    a1[2*q+1] = fma2(wzp, hv.y, a1[2*q+1]);
                    a2[2*q]   = fma2(wnp, hv.x, a2[2*q]);
                    a2[2*q+1] = fma2(wnp, hv.y, a2[2*q+1]);
                }
            }
            const float* xbase = xg + ((size_t)t * NB + b0) * G;
#pragma unroll
            for (int p = 0; p < 8; ++p) {
                float2 hr = unpack2(a0[p]), hz = unpack2(a1[p]), hq = unpack2(a2[p]);
                int b = 2 * p;
                {
                    const float* xr = xbase + (size_t)b * G;
                    float r  = sigm(xr[j]         + hr.x + bh0);
                    float z  = sigm(xr[H + j]     + hz.x + bh1);
                    float nn = tanhf(xr[2 * H + j] + r * (hq.x + bh2));
                    float hv = (1.f - z) * nn + z * sh[j * BTR + b];
                    hn[b] = hv;
                    if (t < slen[b])
                        out[(size_t)(sstart[b] + t) * (2 * H) + dir * H + j] = hv;
                }
                {
                    int b1 = b + 1;
                    const float* xr = xbase + (size_t)b1 * G;
                    float r  = sigm(xr[j]         + hr.y + bh0);
                    float z  = sigm(xr[H + j]     + hz.y + bh1);
                    float nn = tanhf(xr[2 * H + j] + r * (hq.y + bh2));
                    float hv = (1.f - z) * nn + z * sh[j * BTR + b1];
                    hn[b1] = hv;
                    if (t < slen[b1])
                        out[(size_t)(sstart[b1] + t) * (2 * H) + dir * H + j] = hv;
                }
            }
        }
        __syncthreads();                // all reads of old h complete
        if (j < H) {
#pragma unroll
            for (int b = 0; b < BTR; ++b) sh[j * BTR + b] = hn[b];
        }
        __syncthreads();                // new h visible for next step
    }
}

// ---------------- host entry ----------------
extern "C" void kernel_launch(void* const* d_in, const int* in_sizes, int n_in,
                              void* d_out, int out_size) {
    const float* node   = (const float*)d_in[0];
    const int*   batch  = (const int*)d_in[1];
    const int*   pos    = (const int*)d_in[2];
    const float* bias   = (const float*)d_in[3];
    const float* w_ih_f = (const float*)d_in[4];
    const float* w_hh_f = (const float*)d_in[5];
    const float* b_ih_f = (const float*)d_in[6];
    const float* b_hh_f = (const float*)d_in[7];
    const float* w_ih_b = (const float*)d_in[8];
    const float* w_hh_b = (const float*)d_in[9];
    const float* b_ih_b = (const float*)d_in[10];
    const float* b_hh_b = (const float*)d_in[11];
    float* out = (float*)d_out;
    int n = in_sizes[0] / H;

    k_zero_x<<<2048, 256>>>();
    k_transpose<<<2048, 256>>>(w_ih_f, w_hh_f, w_ih_b, w_hh_b);
    k_seg<<<(n + 255) / 256, 256>>>(batch, pos, n);
    k_message<<<4096, 256>>>(node, batch, pos, bias, n);
    k_h0<<<NB, NTHREADS>>>(node);
    k_gemm16<<<dim3(2048, 2), NTHREADS>>>(b_ih_f, b_ih_b);
    k_recur<<<dim3(NB / BTR, 2), NTHREADS>>>(b_hh_f, b_hh_b, out);
}

// round 2
// speedup vs baseline: 1.4467x; 1.4467x over previous
#include <cuda_runtime.h>
#include <math.h>

#define H     300
#define G     900          // 3*H
#define NB    1024         // graphs
#define LSEQ  64           // max sequence length
#define BTR   16           // graphs per recurrent CTA
#define BTG   32           // node rows per input-GEMM CTA
#define SXP   36           // padded smem stride (floats) for GEMM x tile
#define SHP   20           // padded smem stride (floats) for recur h tile
#define NTHREADS 320       // 10 warps, 300 active compute lanes
#define NNODES 49152       // total nodes (harness passes n; sized for max)

typedef unsigned long long ull;

// ---------------- packed f32x2 helpers (Blackwell FFMA2 via PTX) ----------------
__device__ __forceinline__ ull fma2(ull a, ull b, ull c) {
    ull d; asm("fma.rn.f32x2 %0, %1, %2, %3;" : "=l"(d) : "l"(a), "l"(b), "l"(c)); return d;
}
__device__ __forceinline__ ull pack2(float x, float y) {
    ull d; asm("mov.b64 %0, {%1, %2};" : "=l"(d) : "f"(x), "f"(y)); return d;
}
__device__ __forceinline__ float2 unpack2(ull a) {
    float2 r; asm("mov.b64 {%0, %1}, %2;" : "=f"(r.x), "=f"(r.y) : "l"(a)); return r;
}
__device__ __forceinline__ float sigm(float x) { return 1.f / (1.f + __expf(-x)); }

// ---------------- device scratch (static: no allocations allowed) ----------------
// input-gate preactivations, flat node-indexed: [dir][node i][g]
__device__ float g_xg[2][(size_t)NNODES * G];
__device__ float g_wt_ih[2][H * G];   // k-major transposed w_ih
__device__ float g_wt_hh[2][H * G];   // k-major transposed w_hh
__device__ float g_h0[NB * H];
__device__ int   g_sstart[NB];
__device__ int   g_slen[NB];

// ---------------- 1) segment bounds (batch is sorted, no atomics) ----------------
__global__ void k_seg(const int* __restrict__ batch, const int* __restrict__ pos, int n) {
    int i = blockIdx.x * blockDim.x + threadIdx.x;
    if (i >= n) return;
    int b = batch[i];
    if (pos[i] == 0) g_sstart[b] = i;
    if (i == n - 1 || batch[i + 1] != b) g_slen[b] = pos[i] + 1;
}

// ---------------- 2) weight transpose to k-major [k][g] ----------------
__global__ void k_transpose(const float* __restrict__ wif, const float* __restrict__ whf,
                            const float* __restrict__ wib, const float* __restrict__ whb) {
    const int tot = 4 * H * G;
    for (int idx = blockIdx.x * blockDim.x + threadIdx.x; idx < tot;
         idx += gridDim.x * blockDim.x) {
        int sel = idx / (H * G), r = idx - sel * (H * G);
        int g = r / H, k = r - g * H;
        const float* src = (sel == 0) ? wif : (sel == 1) ? whf : (sel == 2) ? wib : whb;
        float* dst = (sel == 0) ? g_wt_ih[0] : (sel == 1) ? g_wt_hh[0]
                   : (sel == 2) ? g_wt_ih[1] : g_wt_hh[1];
        dst[k * G + g] = src[r];
    }
}

// ---------------- 3) h0 = per-graph segment max ----------------
__global__ void __launch_bounds__(NTHREADS) k_h0(const float* __restrict__ node) {
    int b = blockIdx.x, h = threadIdx.x;
    if (h >= H) return;
    int s = g_sstart[b], l = g_slen[b];
    float m = -3.402823466e38f;
    for (int i = 0; i < l; ++i) m = fmaxf(m, node[(size_t)(s + i) * H + h]);
    g_h0[b * H + h] = m;
}

// ---------------- 4) input GEMM over FLAT nodes, message fused ----------------
// xg[dir][i][g] = relu(node[i]+bias) @ w_ih^T + b_ih   (32 rows per CTA)
__global__ void __launch_bounds__(NTHREADS, 1) k_gemm(const float* __restrict__ node,
                                                      const float* __restrict__ bias,
                                                      const float* __restrict__ bih_f,
                                                      const float* __restrict__ bih_b,
                                                      int n) {
    int dir = blockIdx.y;
    int i0 = blockIdx.x * BTG;
    __shared__ float sx[H * SXP];                 // [k][row], padded stride 36
    {   // coalesced load + fused relu(node+bias) + transpose store (4-way STS conflict)
        const int tot = BTG * H;
        for (int idx = threadIdx.x; idx < tot; idx += NTHREADS) {
            int r = idx / H, k = idx - r * H;     // consecutive threads -> consecutive k
            float v = node[(size_t)(i0 + r) * H + k] + bias[k];
            sx[k * SXP + r] = v > 0.f ? v : 0.f;
        }
    }
    __syncthreads();
    int j = threadIdx.x;
    if (j >= H) return;

    const float* __restrict__ w0 = g_wt_ih[dir] + j;
    ull a0[16], a1[16], a2[16];
#pragma unroll
    for (int p = 0; p < 16; ++p) { a0[p] = 0ull; a1[p] = 0ull; a2[p] = 0ull; }

#pragma unroll 4
    for (int k = 0; k < H; ++k) {
        float wr = w0[k * G], wz = w0[k * G + H], wn = w0[k * G + 2 * H];
        ull wrp = pack2(wr, wr), wzp = pack2(wz, wz), wnp = pack2(wn, wn);
        const ulonglong2* hp = (const ulonglong2*)(sx + k * SXP);
#pragma unroll
        for (int q = 0; q < 8; ++q) {
            ulonglong2 hv = hp[q];
            a0[2*q]   = fma2(wrp, hv.x, a0[2*q]);
            a0[2*q+1] = fma2(wrp, hv.y, a0[2*q+1]);
            a1[2*q]   = fma2(wzp, hv.x, a1[2*q]);
            a1[2*q+1] = fma2(wzp, hv.y, a1[2*q+1]);
            a2[2*q]   = fma2(wnp, hv.x, a2[2*q]);
            a2[2*q+1] = fma2(wnp, hv.y, a2[2*q+1]);
        }
    }

    const float* bih = dir ? bih_b : bih_f;
    float bi0 = bih[j], bi1 = bih[H + j], bi2 = bih[2 * H + j];
    float* xg = g_xg[dir];
#pragma unroll
    for (int p = 0; p < 16; ++p) {
        float2 v0 = unpack2(a0[p]), v1 = unpack2(a1[p]), v2 = unpack2(a2[p]);
        float* r0 = xg + (size_t)(i0 + 2 * p)     * G;
        float* r1 = xg + (size_t)(i0 + 2 * p + 1) * G;
        r0[j] = v0.x + bi0; r0[H + j] = v1.x + bi1; r0[2 * H + j] = v2.x + bi2;
        r1[j] = v0.y + bi0; r1[H + j] = v1.y + bi1; r1[2 * H + j] = v2.y + bi2;
    }
}

// ---------------- 5) recurrent GRU, both directions, batch-partitioned ----------------
__global__ void __launch_bounds__(NTHREADS, 1) k_recur(const float* __restrict__ bih_f,
                                                       const float* __restrict__ bih_b,
                                                       const float* __restrict__ bhh_f,
                                                       const float* __restrict__ bhh_b,
                                                       float* __restrict__ out) {
    int dir = blockIdx.y;
    int b0 = blockIdx.x * BTR;
    __shared__ float sh[H * SHP];                 // h, k-major, padded stride 20
    __shared__ int sstart[BTR], slen[BTR];

    if (threadIdx.x < BTR) {
        sstart[threadIdx.x] = g_sstart[b0 + threadIdx.x];
        slen[threadIdx.x]   = g_slen[b0 + threadIdx.x];
    }
    {
        int j = threadIdx.x;
        if (j < H) {
#pragma unroll
            for (int b = 0; b < BTR; ++b) sh[j * SHP + b] = g_h0[(b0 + b) * H + j];
        }
    }
    __syncthreads();

    int j = threadIdx.x;                          // hidden unit owned by this thread
    const float* __restrict__ w0  = g_wt_hh[dir] + j;
    const float* __restrict__ bhh = dir ? bhh_b : bhh_f;
    const float* __restrict__ bih = dir ? bih_b : bih_f;
    const float* __restrict__ xg  = g_xg[dir];
    float bh0 = 0.f, bh1 = 0.f, bh2 = 0.f, bi0 = 0.f, bi1 = 0.f, bi2 = 0.f;
    if (j < H) {
        bh0 = bhh[j]; bh1 = bhh[H + j]; bh2 = bhh[2 * H + j];
        bi0 = bih[j]; bi1 = bih[H + j]; bi2 = bih[2 * H + j];
    }

    for (int s = 0; s < LSEQ; ++s) {
        int t = dir ? (LSEQ - 1 - s) : s;
        float hn[BTR];
        if (j < H) {
            ull a0[8], a1[8], a2[8];
#pragma unroll
            for (int p = 0; p < 8; ++p) { a0[p] = 0ull; a1[p] = 0ull; a2[p] = 0ull; }
#pragma unroll 4
            for (int k = 0; k < H; ++k) {
                float wr = w0[k * G], wz = w0[k * G + H], wn = w0[k * G + 2 * H];
                ull wrp = pack2(wr, wr), wzp = pack2(wz, wz), wnp = pack2(wn, wn);
                const ulonglong2* hp = (const ulonglong2*)(sh + k * SHP);
#pragma unroll
                for (int q = 0; q < 4; ++q) {
                    ulonglong2 hv = hp[q];
                    a0[2*q]   = fma2(wrp, hv.x, a0[2*q]);
                    a0[2*q+1] = fma2(wrp, hv.y, a0[2*q+1]);
                    a1[2*q]   = fma2(wzp, hv.x, a1[2*q]);
                    a1[2*q+1] = fma2(wzp, hv.y, a1[2*q+1]);
                    a2[2*q]   = fma2(wnp, hv.x, a2[2*q]);
                    a2[2*q+1] = fma2(wnp, hv.y, a2[2*q+1]);
                }
            }
#pragma unroll
            for (int p = 0; p < 8; ++p) {
                float2 hr = unpack2(a0[p]), hz = unpack2(a1[p]), hq = unpack2(a2[p]);
#pragma unroll
                for (int e = 0; e < 2; ++e) {
                    int b = 2 * p + e;
                    float hrv = e ? hr.y : hr.x, hzv = e ? hz.y : hz.x, hqv = e ? hq.y : hq.x;
                    bool valid = (t < slen[b]);
                    float x0 = bi0, x1 = bi1, x2 = bi2;
                    size_t ni = (size_t)(sstart[b] + t);
                    if (valid) {
                        const float* xr = xg + ni * G;
                        x0 = xr[j]; x1 = xr[H + j]; x2 = xr[2 * H + j];
                    }
                    float r  = sigm(x0 + hrv + bh0);
                    float z  = sigm(x1 + hzv + bh1);
                    float nn = tanhf(x2 + r * (hqv + bh2));
                    float hv = (1.f - z) * nn + z * sh[j * SHP + b];
                    hn[b] = hv;
                    if (valid)
                        out[ni * (2 * H) + dir * H + j] = hv;
                }
            }
        }
        __syncthreads();                // all reads of old h complete
        if (j < H) {
#pragma unroll
            for (int b = 0; b < BTR; ++b) sh[j * SHP + b] = hn[b];
        }
        __syncthreads();                // new h visible for next step
    }
}

// ---------------- host entry ----------------
extern "C" void kernel_launch(void* const* d_in, const int* in_sizes, int n_in,
                              void* d_out, int out_size) {
    const float* node   = (const float*)d_in[0];
    const int*   batch  = (const int*)d_in[1];
    const int*   pos    = (const int*)d_in[2];
    const float* bias   = (const float*)d_in[3];
    const float* w_ih_f = (const float*)d_in[4];
    const float* w_hh_f = (const float*)d_in[5];
    const float* b_ih_f = (const float*)d_in[6];
    const float* b_hh_f = (const float*)d_in[7];
    const float* w_ih_b = (const float*)d_in[8];
    const float* w_hh_b = (const float*)d_in[9];
    const float* b_ih_b = (const float*)d_in[10];
    const float* b_hh_b = (const float*)d_in[11];
    float* out = (float*)d_out;
    int n = in_sizes[0] / H;

    k_seg<<<(n + 255) / 256, 256>>>(batch, pos, n);
    k_transpose<<<2048, 256>>>(w_ih_f, w_hh_f, w_ih_b, w_hh_b);
    k_h0<<<NB, NTHREADS>>>(node);
    k_gemm<<<dim3(n / BTG, 2), NTHREADS>>>(node, bias, b_ih_f, b_ih_b, n);
    k_recur<<<dim3(NB / BTR, 2), NTHREADS>>>(b_ih_f, b_ih_b, b_hh_f, b_hh_b, out);
}

// round 4
// speedup vs baseline: 1.8859x; 1.3036x over previous
#include <cuda_runtime.h>
#include <cuda_bf16.h>
#include <math.h>
#include <cstdint>

#define H     300
#define G     900
#define NB    1024
#define LSEQ  64
#define BTR   16
#define SHP   20
#define NTHREADS 320
#define NNODES 49152

// ---- tensor GEMM config (mma.sync path, base-target PTX) ----
#define KP  960            // split-K: 3 sections of 320 ([hi|lo|hi] x [hi|hi|lo])
#define NP  1024           // padded N (900 -> 1024)
#define MT  128            // M rows per CTA
#define NKB2 (KP / 32)     // 30 k-chunks of 32
#define SROW 80            // smem row stride bytes (32 bf16 = 64B data + 16B pad)

typedef unsigned long long ull;

// ---------------- packed f32x2 helpers ----------------
__device__ __forceinline__ ull fma2(ull a, ull b, ull c) {
    ull d; asm("fma.rn.f32x2 %0, %1, %2, %3;" : "=l"(d) : "l"(a), "l"(b), "l"(c)); return d;
}
__device__ __forceinline__ ull pack2(float x, float y) {
    ull d; asm("mov.b64 %0, {%1, %2};" : "=l"(d) : "f"(x), "f"(y)); return d;
}
__device__ __forceinline__ float2 unpack2(ull a) {
    float2 r; asm("mov.b64 {%0, %1}, %2;" : "=f"(r.x), "=f"(r.y) : "l"(a)); return r;
}
__device__ __forceinline__ float sigm(float x) { return 1.f / (1.f + __expf(-x)); }
__device__ __forceinline__ uint32_t smem_u32(const void* p) {
    uint32_t a;
    asm("{ .reg .u64 t; cvta.to.shared.u64 t, %1; cvt.u32.u64 %0, t; }" : "=r"(a) : "l"(p));
    return a;
}

// ---------------- device scratch ----------------
__device__ __align__(16) __nv_bfloat16 g_abf[(size_t)NNODES * KP];   // A' = [hi|lo|hi]
__device__ __align__(16) __nv_bfloat16 g_bbf[2][(size_t)NP * KP];    // B' = [hi|hi|lo]
__device__ float g_xg[2][(size_t)NNODES * G];                        // x-gate preacts (+b_ih)
__device__ float g_wt_hh[2][H * G];                                  // k-major w_hh
__device__ float g_h0[NB * H];
__device__ int   g_sstart[NB];
__device__ int   g_slen[NB];

// ---------------- 1) segment bounds ----------------
__global__ void k_seg(const int* __restrict__ batch, const int* __restrict__ pos, int n) {
    int i = blockIdx.x * blockDim.x + threadIdx.x;
    if (i >= n) return;
    int b = batch[i];
    if (pos[i] == 0) g_sstart[b] = i;
    if (i == n - 1 || batch[i + 1] != b) g_slen[b] = pos[i] + 1;
}

// ---------------- 2) w_hh transpose to k-major ----------------
__global__ void k_transpose(const float* __restrict__ whf, const float* __restrict__ whb) {
    const int tot = 2 * H * G;
    for (int idx = blockIdx.x * blockDim.x + threadIdx.x; idx < tot;
         idx += gridDim.x * blockDim.x) {
        int sel = idx / (H * G), r = idx - sel * (H * G);
        int g = r / H, k = r - g * H;
        const float* src = sel ? whb : whf;
        float* dst = sel ? g_wt_hh[1] : g_wt_hh[0];
        dst[k * G + g] = src[r];
    }
}

// ---------------- 3) h0 = per-graph segment max ----------------
__global__ void __launch_bounds__(NTHREADS) k_h0(const float* __restrict__ node) {
    int b = blockIdx.x, h = threadIdx.x;
    if (h >= H) return;
    int s = g_sstart[b], l = g_slen[b];
    float m = -3.402823466e38f;
    for (int i = 0; i < l; ++i) m = fmaxf(m, node[(size_t)(s + i) * H + h]);
    g_h0[b * H + h] = m;
}

// ---------------- 4) A' = split-bf16 of relu(node + bias), K-concatenated ----------------
__global__ void k_convA(const float* __restrict__ node, const float* __restrict__ bias, int n) {
    size_t tot = (size_t)n * KP;
    for (size_t idx = (size_t)blockIdx.x * blockDim.x + threadIdx.x; idx < tot;
         idx += (size_t)gridDim.x * blockDim.x) {
        size_t i = idx / KP;
        int kp = (int)(idx - i * KP);
        __nv_bfloat16 o = __float2bfloat16(0.f);
        int k = -1; bool lo = false;
        if (kp < 300)                    { k = kp; }
        else if (kp >= 320 && kp < 620)  { k = kp - 320; lo = true; }
        else if (kp >= 640 && kp < 940)  { k = kp - 640; }
        if (k >= 0) {
            float m = node[i * H + k] + bias[k];
            m = m > 0.f ? m : 0.f;
            __nv_bfloat16 hi = __float2bfloat16(m);
            o = lo ? __float2bfloat16(m - __bfloat162float(hi)) : hi;
        }
        g_abf[idx] = o;
    }
}

// ---------------- 5) B' = split-bf16 of w_ih, K-concatenated, N padded ----------------
__global__ void k_convB(const float* __restrict__ wif, const float* __restrict__ wib) {
    size_t tot = (size_t)2 * NP * KP;
    for (size_t idx = (size_t)blockIdx.x * blockDim.x + threadIdx.x; idx < tot;
         idx += (size_t)gridDim.x * blockDim.x) {
        int dir = (int)(idx / ((size_t)NP * KP));
        size_t r = idx - (size_t)dir * NP * KP;
        int g = (int)(r / KP), kp = (int)(r - (size_t)g * KP);
        __nv_bfloat16 o = __float2bfloat16(0.f);
        int k = -1; bool lo = false;
        if (kp < 300)                    { k = kp; }
        else if (kp >= 320 && kp < 620)  { k = kp - 320; }
        else if (kp >= 640 && kp < 940)  { k = kp - 640; lo = true; }
        if (k >= 0 && g < G) {
            const float* w = dir ? wib : wif;
            float v = w[(size_t)g * H + k];
            __nv_bfloat16 hi = __float2bfloat16(v);
            o = lo ? __float2bfloat16(v - __bfloat162float(hi)) : hi;
        }
        g_bbf[dir][r] = o;
    }
}

// ---------------- 6) input GEMM via mma.sync bf16: xg = A' @ B'^T + b_ih ----------------
__global__ void __launch_bounds__(256, 2) k_gemm_mma(const float* __restrict__ bih_f,
                                                     const float* __restrict__ bih_b) {
    __shared__ __align__(16) unsigned char sA[2][MT * SROW];
    __shared__ __align__(16) unsigned char sB[2][128 * SROW];
    const int tid = threadIdx.x, lane = tid & 31, wid = tid >> 5;
    const int dir = blockIdx.x >> 3, ntile = blockIdx.x & 7;
    const int m0 = blockIdx.y * MT, n0 = ntile * 128;
    const int wm = wid & 3, wn = wid >> 2;   // 4 x 2 warp grid

    const __nv_bfloat16* __restrict__ A = g_abf + (size_t)m0 * KP;
    const __nv_bfloat16* __restrict__ B = g_bbf[dir] + (size_t)n0 * KP;
    const uint32_t sA0 = smem_u32(sA), sB0 = smem_u32(sB);

    float d[2][8][4];
#pragma unroll
    for (int mi = 0; mi < 2; ++mi)
#pragma unroll
        for (int ni = 0; ni < 8; ++ni)
#pragma unroll
            for (int e = 0; e < 4; ++e) d[mi][ni][e] = 0.f;

    // ---- stage loader (cp.async, 16B) ----
#define ISSUE_STAGE(kb) do {                                                        \
    int _buf = (kb) & 1;                                                            \
    _Pragma("unroll")                                                               \
    for (int _p = 0; _p < 2; ++_p) {                                                \
        int _u = _p * 256 + tid, _row = _u >> 2, _c = _u & 3;                       \
        const void* _ga = A + (size_t)_row * KP + (kb) * 32 + _c * 8;               \
        uint32_t _da = sA0 + _buf * (MT * SROW) + _row * SROW + _c * 16;            \
        asm volatile("cp.async.cg.shared.global [%0], [%1], 16;" :: "r"(_da), "l"(_ga)); \
        const void* _gb = B + (size_t)_row * KP + (kb) * 32 + _c * 8;               \
        uint32_t _db = sB0 + _buf * (128 * SROW) + _row * SROW + _c * 16;           \
        asm volatile("cp.async.cg.shared.global [%0], [%1], 16;" :: "r"(_db), "l"(_gb)); \
    }                                                                               \
    asm volatile("cp.async.commit_group;" ::: "memory");                            \
} while (0)

    ISSUE_STAGE(0);
    for (int kb = 0; kb < NKB2; ++kb) {
        if (kb + 1 < NKB2) {
            ISSUE_STAGE(kb + 1);
            asm volatile("cp.async.wait_group 1;" ::: "memory");
        } else {
            asm volatile("cp.async.wait_group 0;" ::: "memory");
        }
        __syncthreads();
        const uint32_t* a32 = (const uint32_t*)(sA[kb & 1]);
        const uint32_t* b32 = (const uint32_t*)(sB[kb & 1]);
#pragma unroll
        for (int ks = 0; ks < 2; ++ks) {
            uint32_t af[2][4];
#pragma unroll
            for (int mi = 0; mi < 2; ++mi) {
                int r0 = wm * 32 + mi * 16 + (lane >> 2);
                af[mi][0] = a32[r0 * 20 + ks * 8 + (lane & 3)];
                af[mi][1] = a32[(r0 + 8) * 20 + ks * 8 + (lane & 3)];
                af[mi][2] = a32[r0 * 20 + ks * 8 + 4 + (lane & 3)];
                af[mi][3] = a32[(r0 + 8) * 20 + ks * 8 + 4 + (lane & 3)];
            }
#pragma unroll
            for (int ni = 0; ni < 8; ++ni) {
                int cn = wn * 64 + ni * 8 + (lane >> 2);
                uint32_t b0 = b32[cn * 20 + ks * 8 + (lane & 3)];
                uint32_t b1 = b32[cn * 20 + ks * 8 + 4 + (lane & 3)];
#pragma unroll
                for (int mi = 0; mi < 2; ++mi) {
                    asm volatile(
                        "mma.sync.aligned.m16n8k16.row.col.f32.bf16.bf16.f32 "
                        "{%0,%1,%2,%3}, {%4,%5,%6,%7}, {%8,%9}, {%0,%1,%2,%3};"
                        : "+f"(d[mi][ni][0]), "+f"(d[mi][ni][1]),
                          "+f"(d[mi][ni][2]), "+f"(d[mi][ni][3])
                        : "r"(af[mi][0]), "r"(af[mi][1]), "r"(af[mi][2]), "r"(af[mi][3]),
                          "r"(b0), "r"(b1));
                }
            }
        }
        __syncthreads();
    }
#undef ISSUE_STAGE

    // ---- epilogue: +b_ih, crop to G=900, write fp32 ----
    const float* __restrict__ bih = dir ? bih_b : bih_f;
    float* __restrict__ xg = g_xg[dir];
#pragma unroll
    for (int mi = 0; mi < 2; ++mi) {
        int r0 = m0 + wm * 32 + mi * 16 + (lane >> 2);
#pragma unroll
        for (int ni = 0; ni < 8; ++ni) {
            int g = n0 + wn * 64 + ni * 8 + (lane & 3) * 2;
            if (g < G) {
                float bg0 = bih[g], bg1 = bih[g + 1];
                *(float2*)(xg + (size_t)r0 * G + g) =
                    make_float2(d[mi][ni][0] + bg0, d[mi][ni][1] + bg1);
                *(float2*)(xg + (size_t)(r0 + 8) * G + g) =
                    make_float2(d[mi][ni][2] + bg0, d[mi][ni][3] + bg1);
            }
        }
    }
}

// ---------------- streaming load/store hints ----------------
__device__ __forceinline__ float ldcs(const float* p) {
    float v; asm volatile("ld.global.cs.f32 %0, [%1];" : "=f"(v) : "l"(p)); return v;
}
__device__ __forceinline__ void stcs(float* p, float v) {
    asm volatile("st.global.cs.f32 [%0], %1;" :: "l"(p), "f"(v));
}

// ---------------- 7) recurrent GRU (FFMA2, batch-partitioned) ----------------
__global__ void __launch_bounds__(NTHREADS, 1) k_recur(const float* __restrict__ bih_f,
                                                       const float* __restrict__ bih_b,
                                                       const float* __restrict__ bhh_f,
                                                       const float* __restrict__ bhh_b,
                                                       float* __restrict__ out) {
    int dir = blockIdx.y;
    int b0 = blockIdx.x * BTR;
    __shared__ float sh[H * SHP];
    __shared__ int sstart[BTR], slen[BTR];

    if (threadIdx.x < BTR) {
        sstart[threadIdx.x] = g_sstart[b0 + threadIdx.x];
        slen[threadIdx.x]   = g_slen[b0 + threadIdx.x];
    }
    {
        int j = threadIdx.x;
        if (j < H) {
#pragma unroll
            for (int b = 0; b < BTR; ++b) sh[j * SHP + b] = g_h0[(b0 + b) * H + j];
        }
    }
    __syncthreads();

    int j = threadIdx.x;
    const float* __restrict__ w0  = g_wt_hh[dir] + j;
    const float* __restrict__ bhh = dir ? bhh_b : bhh_f;
    const float* __restrict__ bih = dir ? bih_b : bih_f;
    const float* __restrict__ xg  = g_xg[dir];
    float bh0 = 0.f, bh1 = 0.f, bh2 = 0.f, bi0 = 0.f, bi1 = 0.f, bi2 = 0.f;
    if (j < H) {
        bh0 = bhh[j]; bh1 = bhh[H + j]; bh2 = bhh[2 * H + j];
        bi0 = bih[j]; bi1 = bih[H + j]; bi2 = bih[2 * H + j];
    }

    for (int s = 0; s < LSEQ; ++s) {
        int t = dir ? (LSEQ - 1 - s) : s;
        float hn[BTR];
        if (j < H) {
            ull a0[8], a1[8], a2[8];
#pragma unroll
            for (int p = 0; p < 8; ++p) { a0[p] = 0ull; a1[p] = 0ull; a2[p] = 0ull; }

            // software-pipelined weight prefetch: 4-k blocks, double-buffered regs
            float wb[2][12];
#pragma unroll
            for (int q = 0; q < 4; ++q) {
                wb[0][3*q]   = w0[q * G];
                wb[0][3*q+1] = w0[q * G + H];
                wb[0][3*q+2] = w0[q * G + 2 * H];
            }
#pragma unroll 2
            for (int kb = 0; kb < H / 4; ++kb) {
                int cur = kb & 1, nxt = cur ^ 1;
                if (kb < H / 4 - 1) {
#pragma unroll
                    for (int q = 0; q < 4; ++q) {
                        int k = (kb + 1) * 4 + q;
                        wb[nxt][3*q]   = w0[k * G];
                        wb[nxt][3*q+1] = w0[k * G + H];
                        wb[nxt][3*q+2] = w0[k * G + 2 * H];
                    }
                }
#pragma unroll
                for (int q = 0; q < 4; ++q) {
                    int k = kb * 4 + q;
                    float wr = wb[cur][3*q], wz = wb[cur][3*q+1], wn = wb[cur][3*q+2];
                    ull wrp = pack2(wr, wr), wzp = pack2(wz, wz), wnp = pack2(wn, wn);
                    const ulonglong2* hp = (const ulonglong2*)(sh + k * SHP);
#pragma unroll
                    for (int qq = 0; qq < 4; ++qq) {
                        ulonglong2 hv = hp[qq];
                        a0[2*qq]   = fma2(wrp, hv.x, a0[2*qq]);
                        a0[2*qq+1] = fma2(wrp, hv.y, a0[2*qq+1]);
                        a1[2*qq]   = fma2(wzp, hv.x, a1[2*qq]);
                        a1[2*qq+1] = fma2(wzp, hv.y, a1[2*qq+1]);
                        a2[2*qq]   = fma2(wnp, hv.x, a2[2*qq]);
                        a2[2*qq+1] = fma2(wnp, hv.y, a2[2*qq+1]);
                    }
                }
            }
#pragma unroll
            for (int p = 0; p < 8; ++p) {
                float2 hr = unpack2(a0[p]), hz = unpack2(a1[p]), hq = unpack2(a2[p]);
#pragma unroll
                for (int e = 0; e < 2; ++e) {
                    int b = 2 * p + e;
                    float hrv = e ? hr.y : hr.x, hzv = e ? hz.y : hz.x, hqv = e ? hq.y : hq.x;
                    bool valid = (t < slen[b]);
                    float x0 = bi0, x1 = bi1, x2 = bi2;
                    size_t ni = (size_t)(sstart[b] + t);
                    if (valid) {
                        const float* xr = xg + ni * G;
                        x0 = ldcs(xr + j); x1 = ldcs(xr + H + j); x2 = ldcs(xr + 2 * H + j);
                    }
                    float r  = sigm(x0 + hrv + bh0);
                    float z  = sigm(x1 + hzv + bh1);
                    float nn = tanhf(x2 + r * (hqv + bh2));
                    float hv = (1.f - z) * nn + z * sh[j * SHP + b];
                    hn[b] = hv;
                    if (valid)
                        stcs(out + ni * (2 * H) + dir * H + j, hv);
                }
            }
        }
        __syncthreads();
        if (j < H) {
#pragma unroll
            for (int b = 0; b < BTR; ++b) sh[j * SHP + b] = hn[b];
        }
        __syncthreads();
    }
}

// ---------------- host entry ----------------
extern "C" void kernel_launch(void* const* d_in, const int* in_sizes, int n_in,
                              void* d_out, int out_size) {
    const float* node   = (const float*)d_in[0];
    const int*   batch  = (const int*)d_in[1];
    const int*   pos    = (const int*)d_in[2];
    const float* bias   = (const float*)d_in[3];
    const float* w_ih_f = (const float*)d_in[4];
    const float* w_hh_f = (const float*)d_in[5];
    const float* b_ih_f = (const float*)d_in[6];
    const float* b_hh_f = (const float*)d_in[7];
    const float* w_ih_b = (const float*)d_in[8];
    const float* w_hh_b = (const float*)d_in[9];
    const float* b_ih_b = (const float*)d_in[10];
    const float* b_hh_b = (const float*)d_in[11];
    float* out = (float*)d_out;
    int n = in_sizes[0] / H;

    k_seg<<<(n + 255) / 256, 256>>>(batch, pos, n);
    k_transpose<<<2048, 256>>>(w_hh_f, w_hh_b);
    k_h0<<<NB, NTHREADS>>>(node);
    k_convA<<<4096, 256>>>(node, bias, n);
    k_convB<<<2048, 256>>>(w_ih_f, w_ih_b);
    k_gemm_mma<<<dim3(16, n / MT), 256>>>(b_ih_f, b_ih_b);
    k_recur<<<dim3(NB / BTR, 2), NTHREADS>>>(b_ih_f, b_ih_b, b_hh_f, b_hh_b, out);
}